// round 16
// baseline (speedup 1.0000x reference)
#include <cuda_runtime.h>
#include <cuda_bf16.h>
#include <cstdint>

#define NB 2
#define VD 4
#define ID 32
#define SD 64
#define KS 8
#define HD 128
#define G0 80
#define G1 78
#define G2 76
#define G3 74
#define N3 405224

__device__ uint4 g_x1b[(size_t)NB * G1 * G1 * 80 * 8];
__device__ uint4 g_x2b[(size_t)NB * G2 * G2 * 80 * 8];
__device__ float g_feat[(size_t)NB * N3 * ID];
__device__ uint4 g_wB2[27 * 4608 / 16];
__device__ uint4 g_wB3[27 * 4608 / 16];
__device__ float g_slots[NB * KS * SD];
__device__ float g_qk[NB * KS * ID];
__device__ float g_S[NB * KS];
__device__ float g_Uf[NB * KS * ID];

__device__ __forceinline__ float sigmoidf_(float x) { return 1.f / (1.f + expf(-x)); }
#define FMA2(acc, a, b) \
    asm("fma.rn.f32x2 %0, %1, %2, %3;" : "=l"(acc) : "l"(a), "l"(b), "l"(acc))
__device__ __forceinline__ unsigned long long dup2(float v) {
    unsigned long long r; unsigned u = __float_as_uint(v);
    asm("mov.b64 %0, {%1, %1};" : "=l"(r) : "r"(u)); return r;
}
__device__ __forceinline__ unsigned long long pack2(float lo, float hi) {
    unsigned long long r;
    asm("mov.b64 %0, {%1, %2};" : "=l"(r) : "r"(__float_as_uint(lo)), "r"(__float_as_uint(hi)));
    return r;
}
__device__ __forceinline__ void unpack2(unsigned long long p, float& lo, float& hi) {
    unsigned a, b; asm("mov.b64 {%0, %1}, %2;" : "=r"(a), "=r"(b) : "l"(p));
    lo = __uint_as_float(a); hi = __uint_as_float(b);
}
__device__ __forceinline__ void cp_async16(void* d, const void* s) {
    unsigned sa = (unsigned)__cvta_generic_to_shared(d);
    asm volatile("cp.async.cg.shared.global [%0], [%1], 16;" :: "r"(sa), "l"(s) : "memory");
}
__device__ __forceinline__ void ldsm_x4(uint32_t r[4], uint32_t saddr) {
    asm volatile("ldmatrix.sync.aligned.m8n8.x4.shared.b16 {%0,%1,%2,%3}, [%4];"
        : "=r"(r[0]), "=r"(r[1]), "=r"(r[2]), "=r"(r[3]) : "r"(saddr));
}
__device__ __forceinline__ void mma_bf16(float d[4], const uint32_t a[4], uint32_t b0, uint32_t b1) {
    asm volatile(
        "mma.sync.aligned.m16n8k16.row.col.f32.bf16.bf16.f32 "
        "{%0,%1,%2,%3}, {%4,%5,%6,%7}, {%8,%9}, {%0,%1,%2,%3};"
        : "+f"(d[0]), "+f"(d[1]), "+f"(d[2]), "+f"(d[3])
        : "r"(a[0]), "r"(a[1]), "r"(a[2]), "r"(a[3]), "r"(b0), "r"(b1));
}

__device__ __forceinline__ void store_hilo(uint4* dst, const float* v) {
    unsigned short hb[32], lb[32];
#pragma unroll
    for (int c = 0; c < 32; c++) {
        __nv_bfloat16 h = __float2bfloat16(v[c]);
        hb[c] = __bfloat16_as_ushort(h);
        lb[c] = __bfloat16_as_ushort(__float2bfloat16(v[c] - __bfloat162float(h)));
    }
#pragma unroll
    for (int j = 0; j < 4; j++) {
        uint4 q;
        q.x = hb[8*j+0] | ((uint32_t)hb[8*j+1] << 16);
        q.y = hb[8*j+2] | ((uint32_t)hb[8*j+3] << 16);
        q.z = hb[8*j+4] | ((uint32_t)hb[8*j+5] << 16);
        q.w = hb[8*j+6] | ((uint32_t)hb[8*j+7] << 16);
        dst[j] = q;
        q.x = lb[8*j+0] | ((uint32_t)lb[8*j+1] << 16);
        q.y = lb[8*j+2] | ((uint32_t)lb[8*j+3] << 16);
        q.z = lb[8*j+4] | ((uint32_t)lb[8*j+5] << 16);
        q.w = lb[8*j+6] | ((uint32_t)lb[8*j+7] << 16);
        dst[4 + j] = q;
    }
}

__global__ void init_slots_kernel(const float* __restrict__ s) {
    int t = threadIdx.x;
    if (t < NB * KS * SD) g_slots[t] = s[t];
}

__global__ void wprep_kernel(const float* __restrict__ w2, const float* __restrict__ w3) {
    int i = blockIdx.x * 256 + threadIdx.x;
    if (i >= 27 * 32 * 64) return;
    int k = i & 63, n = (i >> 6) & 31, tile = i >> 11;
    int dx = tile % 3, grp = tile / 3;
    int tap = (grp / 3) * 9 + (grp % 3) * 3 + dx;
    int cin = k & 31;
    bool take_hi = (k < 32);
    size_t dst = (size_t)tile * 4608 + n * 144 + k * 2;
    float a = w2[(n * ID + cin) * 27 + tap];
    __nv_bfloat16 h = __float2bfloat16(a);
    *(__nv_bfloat16*)((char*)g_wB2 + dst) = take_hi ? h : __float2bfloat16(a - __bfloat162float(h));
    a = w3[(n * ID + cin) * 27 + tap];
    h = __float2bfloat16(a);
    *(__nv_bfloat16*)((char*)g_wB3 + dst) = take_hi ? h : __float2bfloat16(a - __bfloat162float(h));
}

__global__ void conv1_kernel(const float* __restrict__ in, const float* __restrict__ w,
                             const float* __restrict__ bias) {
    __shared__ float xs[VD * 648];
    __shared__ float ws[VD * 27 * 32];
    __shared__ float bs[32];
    int tid = threadIdx.x;
    int b = blockIdx.z / 20, d0 = (blockIdx.z % 20) * 4, h0 = blockIdx.y * 4, w0 = blockIdx.x * 16;
    for (int i = tid; i < VD * 27 * 32; i += 256) {
        int co = i & 31, tap = (i >> 5) % 27, cin = i / (27 * 32);
        ws[i] = w[(co * VD + cin) * 27 + tap];
    }
    if (tid < 32) bs[tid] = bias[tid];
    for (int i = tid; i < VD * 648; i += 256) {
        int cin = i / 648, r = i % 648;
        int z = r / 108, y = (r % 108) / 18, x = r % 18;
        int gz = d0 + z, gy = h0 + y, gx = w0 + x;
        float v = 0.f;
        if (gz < G0 && gy < G0 && gx < G0)
            v = in[((b * VD + cin) * G0 + gz) * (G0 * G0) + gy * G0 + gx];
        xs[i] = v;
    }
    __syncthreads();
    int tx = tid & 15, ty = (tid >> 4) & 3, tz = tid >> 6;
    unsigned long long acc2[16];
#pragma unroll
    for (int p = 0; p < 16; p++) acc2[p] = 0ull;
    for (int cin = 0; cin < VD; cin++) {
        const float* xb = &xs[cin * 648 + tz * 108 + ty * 18 + tx];
        const float* wb = &ws[cin * 27 * 32];
#pragma unroll
        for (int tap = 0; tap < 27; tap++) {
            int dz = tap / 9, dy = (tap / 3) % 3, dx = tap % 3;
            unsigned long long xv2 = dup2(xb[dz * 108 + dy * 18 + dx]);
            const ulonglong2* w4 = (const ulonglong2*)&wb[tap * 32];
#pragma unroll
            for (int g = 0; g < 8; g++) {
                ulonglong2 q = w4[g];
                FMA2(acc2[2 * g + 0], q.x, xv2);
                FMA2(acc2[2 * g + 1], q.y, xv2);
            }
        }
    }
    int oz = d0 + tz, oy = h0 + ty, ox = w0 + tx;
    if (oz < G1 && oy < G1 && ox < G1) {
        float v[32];
#pragma unroll
        for (int p = 0; p < 16; p++) {
            float lo, hi; unpack2(acc2[p], lo, hi);
            v[2 * p + 0] = fmaxf(lo + bs[2 * p + 0], 0.f);
            v[2 * p + 1] = fmaxf(hi + bs[2 * p + 1], 0.f);
        }
        size_t row = ((size_t)(b * G1 + oz) * G1 + oy) * 80 + ox;
        store_hilo(g_x1b + row * 8, v);
    }
}

#define APITCH 11808
#define ABYTES (16 * APITCH)
#define BGRP 13824
template <int STAGE>
__global__ void __launch_bounds__(320, 1)
conv23_mma(const float* __restrict__ bias, const float* __restrict__ lng,
           const float* __restrict__ lnb) {
    constexpr int IDm = (STAGE == 2) ? G1 : G2;
    constexpr int OD  = (STAGE == 2) ? G2 : G3;
    const char* inb = (const char*)((STAGE == 2) ? g_x1b : g_x2b);
    const char* wB  = (const char*)((STAGE == 2) ? g_wB2 : g_wB3);
    extern __shared__ char sm[];
    int tid = threadIdx.x, w = tid >> 5, lane = tid & 31;
    int y0 = blockIdx.x * 2, z0 = blockIdx.y * 2, b = blockIdx.z;
    {
        const int per = (82 - IDm) * 8;
        for (int i = tid; i < 16 * per; i += 320) {
            int row = i / per, rem = i % per;
            *(float4*)(sm + row * APITCH + (IDm + rem / 8) * 144 + (rem & 7) * 16) =
                make_float4(0.f, 0.f, 0.f, 0.f);
        }
    }
    {
        const int per = IDm * 8;
        for (int i = tid; i < 16 * per; i += 320) {
            int row = i / per, rem = i % per;
            int vox = rem >> 3, c = rem & 7;
            size_t rowg = ((size_t)(b * IDm + (z0 + (row >> 2))) * IDm + (y0 + (row & 3))) * 80 + vox;
            cp_async16(sm + row * APITCH + vox * 144 + c * 16, inb + rowg * 128 + c * 16);
        }
    }
    for (int i = tid; i < BGRP / 16; i += 320)
        cp_async16(sm + ABYTES + i * 16, wB + (size_t)i * 16);
    asm volatile("cp.async.commit_group;" ::: "memory");

    int t0 = 2 * w;
    int row0 = t0 / 5, xa0 = (t0 % 5) * 16;
    int t1 = t0 + 1;
    int row1 = t1 / 5, xa1 = (t1 % 5) * 16;
    uint32_t smb = (uint32_t)__cvta_generic_to_shared(sm);
    uint32_t a_off = (uint32_t)(((lane & 7) + ((lane >> 3) & 1) * 8) * 144 + (lane >> 4) * 16);
    uint32_t b_off = (uint32_t)(((lane & 7) + (lane >> 4) * 8) * 144 + ((lane >> 3) & 1) * 16);
    float D[2][4][4];
#pragma unroll
    for (int i = 0; i < 2; i++)
#pragma unroll
        for (int j = 0; j < 4; j++)
#pragma unroll
            for (int q = 0; q < 4; q++) D[i][j][q] = 0.f;

    for (int g = 0; g < 9; g++) {
        int slot = g % 3;
        if (g < 8) {
            int nslot = (g + 1) % 3;
            for (int i = tid; i < BGRP / 16; i += 320)
                cp_async16(sm + ABYTES + nslot * BGRP + i * 16,
                           wB + (size_t)(g + 1) * BGRP + (size_t)i * 16);
            asm volatile("cp.async.commit_group;" ::: "memory");
            asm volatile("cp.async.wait_group 1;" ::: "memory");
        } else {
            asm volatile("cp.async.wait_group 0;" ::: "memory");
        }
        __syncthreads();
        int dz = g / 3, dy = g % 3;
        uint32_t Bf[3][4][2][4];
        uint32_t sB = smb + ABYTES + slot * BGRP + b_off;
#pragma unroll
        for (int dx = 0; dx < 3; dx++)
#pragma unroll
            for (int kc = 0; kc < 4; kc++) {
                uint32_t bt = sB + dx * 4608 + kc * 32;
                ldsm_x4(Bf[dx][kc][0], bt);
                ldsm_x4(Bf[dx][kc][1], bt + 16 * 144);
            }
        uint32_t sA0 = smb + (((row0 >> 1) + dz) * 4 + (row0 & 1) + dy) * APITCH + a_off;
        uint32_t sA1 = smb + (((row1 >> 1) + dz) * 4 + (row1 & 1) + dy) * APITCH + a_off;
        // software pipeline over it = kc*3+dx: prefetch A frags for it+1 before MMAs of it
        uint32_t Ac[2][4], An[2][4];
        ldsm_x4(Ac[0], sA0 + xa0 * 144);
        ldsm_x4(Ac[1], sA1 + xa1 * 144);
#pragma unroll
        for (int it = 0; it < 12; it++) {
            const int kc = it / 3, dx = it % 3;
            const int kx = kc ^ 2;
            if (it < 11) {
                const int kc2 = (it + 1) / 3, dx2 = (it + 1) % 3;
                ldsm_x4(An[0], sA0 + (xa0 + dx2) * 144 + kc2 * 32);
                ldsm_x4(An[1], sA1 + (xa1 + dx2) * 144 + kc2 * 32);
            }
            if (kc < 2) {
                mma_bf16(D[0][0], Ac[0], Bf[dx][kc][0][0], Bf[dx][kc][0][1]);
                mma_bf16(D[1][0], Ac[1], Bf[dx][kc][0][0], Bf[dx][kc][0][1]);
                mma_bf16(D[0][1], Ac[0], Bf[dx][kc][0][2], Bf[dx][kc][0][3]);
                mma_bf16(D[1][1], Ac[1], Bf[dx][kc][0][2], Bf[dx][kc][0][3]);
                mma_bf16(D[0][2], Ac[0], Bf[dx][kc][1][0], Bf[dx][kc][1][1]);
                mma_bf16(D[1][2], Ac[1], Bf[dx][kc][1][0], Bf[dx][kc][1][1]);
                mma_bf16(D[0][3], Ac[0], Bf[dx][kc][1][2], Bf[dx][kc][1][3]);
                mma_bf16(D[1][3], Ac[1], Bf[dx][kc][1][2], Bf[dx][kc][1][3]);
            }
            mma_bf16(D[0][0], Ac[0], Bf[dx][kx][0][0], Bf[dx][kx][0][1]);
            mma_bf16(D[1][0], Ac[1], Bf[dx][kx][0][0], Bf[dx][kx][0][1]);
            mma_bf16(D[0][1], Ac[0], Bf[dx][kx][0][2], Bf[dx][kx][0][3]);
            mma_bf16(D[1][1], Ac[1], Bf[dx][kx][0][2], Bf[dx][kx][0][3]);
            mma_bf16(D[0][2], Ac[0], Bf[dx][kx][1][0], Bf[dx][kx][1][1]);
            mma_bf16(D[1][2], Ac[1], Bf[dx][kx][1][0], Bf[dx][kx][1][1]);
            mma_bf16(D[0][3], Ac[0], Bf[dx][kx][1][2], Bf[dx][kx][1][3]);
            mma_bf16(D[1][3], Ac[1], Bf[dx][kx][1][2], Bf[dx][kx][1][3]);
#pragma unroll
            for (int q = 0; q < 4; q++) { Ac[0][q] = An[0][q]; Ac[1][q] = An[1][q]; }
        }
    }
    __syncthreads();
    float* Dsm = (float*)sm;
    int gid = lane >> 2, q4 = lane & 3;
#pragma unroll
    for (int ti = 0; ti < 2; ti++) {
        int mbase = (2 * w + ti) * 16 + gid;
#pragma unroll
        for (int ns = 0; ns < 4; ns++) {
            int co = ns * 8 + q4 * 2;
            *(float2*)&Dsm[mbase * 38 + co]       = make_float2(D[ti][ns][0], D[ti][ns][1]);
            *(float2*)&Dsm[(mbase + 8) * 38 + co] = make_float2(D[ti][ns][2], D[ti][ns][3]);
        }
    }
    __syncthreads();
    {
        int m = tid, row = m / 80, x = m % 80;
        int zout = z0 + (row >> 1), yout = y0 + (row & 1);
        if (x < OD) {
            float v[32];
#pragma unroll
            for (int c = 0; c < 32; c++)
                v[c] = fmaxf(Dsm[m * 38 + c] + bias[c], 0.f);
            if (STAGE == 2) {
                size_t rowo = ((size_t)(b * G2 + zout) * G2 + yout) * 80 + x;
                store_hilo(g_x2b + rowo * 8, v);
            } else {
                float mn = 0.f;
#pragma unroll
                for (int c = 0; c < 32; c++) mn += v[c];
                mn *= (1.f / 32.f);
                float var = 0.f;
#pragma unroll
                for (int c = 0; c < 32; c++) { float d = v[c] - mn; var += d * d; }
                float inv = rsqrtf(var * (1.f / 32.f) + 1e-5f);
                size_t vox = ((size_t)zout * G3 + yout) * G3 + x;
                float4* fp = (float4*)&g_feat[((size_t)b * N3 + vox) * 32];
#pragma unroll
                for (int gq = 0; gq < 8; gq++) {
                    float4 o;
                    o.x = (v[4*gq+0] - mn) * inv * lng[4*gq+0] + lnb[4*gq+0];
                    o.y = (v[4*gq+1] - mn) * inv * lng[4*gq+1] + lnb[4*gq+1];
                    o.z = (v[4*gq+2] - mn) * inv * lng[4*gq+2] + lnb[4*gq+2];
                    o.w = (v[4*gq+3] - mn) * inv * lng[4*gq+3] + lnb[4*gq+3];
                    fp[gq] = o;
                }
            }
        }
    }
}

__global__ void qk_kernel(const float* __restrict__ qlng, const float* __restrict__ qlnb,
                          const float* __restrict__ qw, const float* __restrict__ kw) {
    __shared__ float qln_s[16][64];
    __shared__ float q_s[16][64];
    __shared__ float qw_s[64 * 65];
    __shared__ float kw_s[64 * 33];
    int tid = threadIdx.x, warp = tid >> 5, lane = tid & 31;
    const unsigned FULL = 0xffffffffu;
    if (tid < NB * KS) g_S[tid] = 0.f;
    if (tid < NB * KS * ID) g_Uf[tid] = 0.f;
    for (int i = tid; i < 64 * 64; i += 512) qw_s[(i >> 6) * 65 + (i & 63)] = qw[i];
    for (int i = tid; i < 64 * 32; i += 512) kw_s[(i >> 5) * 33 + (i & 31)] = kw[i];
    float x0 = g_slots[warp * SD + lane], x1 = g_slots[warp * SD + 32 + lane];
    float s = x0 + x1;
#pragma unroll
    for (int o = 16; o; o >>= 1) s += __shfl_xor_sync(FULL, s, o);
    float m = s * (1.f / 64.f);
    float d0 = x0 - m, d1 = x1 - m;
    float v = d0 * d0 + d1 * d1;
#pragma unroll
    for (int o = 16; o; o >>= 1) v += __shfl_xor_sync(FULL, v, o);
    float inv = rsqrtf(v * (1.f / 64.f) + 1e-5f);
    float qa = d0 * inv * qlng[lane] + qlnb[lane];
    float qb = d1 * inv * qlng[lane + 32] + qlnb[lane + 32];
    __syncthreads();
    qln_s[warp][lane] = qa;
    qln_s[warp][lane + 32] = qb;
    __syncwarp();
    float a0 = 0.f, a1 = 0.f;
    for (int e = 0; e < 64; e++) {
        float qe = qln_s[warp][e];
        a0 += qe * qw_s[lane * 65 + e];
        a1 += qe * qw_s[(lane + 32) * 65 + e];
    }
    q_s[warp][lane] = a0; q_s[warp][lane + 32] = a1;
    __syncwarp();
    float qk = 0.f;
    for (int d = 0; d < 64; d++) qk += q_s[warp][d] * kw_s[d * 33 + lane];
    g_qk[warp * ID + lane] = qk * 0.125f;
}

__global__ void attn_kernel(float* __restrict__ attn_out, int write_attn) {
    __shared__ float F[256 * 36];
    __shared__ float A[256 * 9];
    __shared__ float qks[KS * ID];
    int tid = threadIdx.x, b = blockIdx.y;
    int j = blockIdx.x * 256 + tid;
    qks[tid] = g_qk[b * KS * ID + tid];
    bool ok = j < N3;
    unsigned long long f2[16];
    if (ok) {
        const float4* fp = (const float4*)&g_feat[((size_t)b * N3 + j) * 32];
#pragma unroll
        for (int g = 0; g < 8; g++) {
            float4 q = fp[g];
            f2[2 * g + 0] = pack2(q.x, q.y);
            f2[2 * g + 1] = pack2(q.z, q.w);
        }
    } else {
#pragma unroll
        for (int p = 0; p < 16; p++) f2[p] = 0ull;
    }
    {
        float2* Fp = (float2*)&F[tid * 36];
#pragma unroll
        for (int p = 0; p < 16; p++) {
            float lo, hi; unpack2(f2[p], lo, hi);
            Fp[p] = make_float2(lo, hi);
        }
    }
    __syncthreads();
    unsigned long long acc2[8];
#pragma unroll
    for (int i = 0; i < 8; i++) acc2[i] = 0ull;
#pragma unroll
    for (int p = 0; p < 16; p++) {
        unsigned long long fp2 = f2[p];
#pragma unroll
        for (int i = 0; i < 8; i++)
            FMA2(acc2[i], fp2, *(const unsigned long long*)&qks[i * 32 + 2 * p]);
    }
    float a[8];
    if (ok) {
        float d[8];
#pragma unroll
        for (int i = 0; i < 8; i++) {
            float lo, hi; unpack2(acc2[i], lo, hi);
            d[i] = lo + hi;
        }
        float m = d[0];
#pragma unroll
        for (int i = 1; i < 8; i++) m = fmaxf(m, d[i]);
        float sum = 0.f;
#pragma unroll
        for (int i = 0; i < 8; i++) { a[i] = __expf(d[i] - m); sum += a[i]; }
        float rs = 1.f / sum;
#pragma unroll
        for (int i = 0; i < 8; i++) a[i] = a[i] * rs + 1e-8f;
        if (write_attn)
#pragma unroll
            for (int i = 0; i < 8; i++)
                attn_out[(size_t)(b * KS + i) * N3 + j] = a[i];
    } else {
#pragma unroll
        for (int i = 0; i < 8; i++) a[i] = 0.f;
    }
#pragma unroll
    for (int i = 0; i < 8; i++) A[tid * 9 + i] = a[i];
    __syncthreads();
    const unsigned FULL = 0xffffffffu;
    int ii = tid >> 5, lane = tid & 31;
    int cp = lane & 15, ph = lane >> 4;
    unsigned long long s2a = 0ull, s2b = 0ull, s2c = 0ull, s2d = 0ull;
    int pb = ph * 128;
#pragma unroll 8
    for (int p0 = 0; p0 < 128; p0 += 4) {
        int p = pb + p0;
        FMA2(s2a, dup2(A[(p + 0) * 9 + ii]), *(const unsigned long long*)&F[(p + 0) * 36 + 2 * cp]);
        FMA2(s2b, dup2(A[(p + 1) * 9 + ii]), *(const unsigned long long*)&F[(p + 1) * 36 + 2 * cp]);
        FMA2(s2c, dup2(A[(p + 2) * 9 + ii]), *(const unsigned long long*)&F[(p + 2) * 36 + 2 * cp]);
        FMA2(s2d, dup2(A[(p + 3) * 9 + ii]), *(const unsigned long long*)&F[(p + 3) * 36 + 2 * cp]);
    }
    float slo, shi, t1, t2;
    unpack2(s2a, slo, shi);
    unpack2(s2b, t1, t2); slo += t1; shi += t2;
    unpack2(s2c, t1, t2); slo += t1; shi += t2;
    unpack2(s2d, t1, t2); slo += t1; shi += t2;
    slo += __shfl_xor_sync(FULL, slo, 16);
    shi += __shfl_xor_sync(FULL, shi, 16);
    if (ph == 0) {
        atomicAdd(&g_Uf[(b * KS + ii) * ID + 2 * cp + 0], slo);
        atomicAdd(&g_Uf[(b * KS + ii) * ID + 2 * cp + 1], shi);
    }
    float ss = 0.f;
#pragma unroll
    for (int q = 0; q < 8; q++) ss += A[(lane + 32 * q) * 9 + ii];
#pragma unroll
    for (int o = 16; o; o >>= 1) ss += __shfl_xor_sync(FULL, ss, o);
    if (lane == 0) atomicAdd(&g_S[b * KS + ii], ss);
}

#define WIH_OFF 0
#define WHH_OFF 12480
#define RW1_OFF 24960
#define RW2_OFF 33280
#define VW_OFF  41536
#define UPD_SMEM ((41536 + 2112) * 4)
__global__ void update_kernel(const float* __restrict__ vw, const float* __restrict__ wih,
                              const float* __restrict__ whh, const float* __restrict__ bih,
                              const float* __restrict__ bhh, const float* __restrict__ rlng,
                              const float* __restrict__ rlnb, const float* __restrict__ rw1,
                              const float* __restrict__ rb1, const float* __restrict__ rw2,
                              const float* __restrict__ rb2, float* __restrict__ out_slots,
                              int last) {
    extern __shared__ float smw[];
    int tid = threadIdx.x, r = tid >> 5, lane = tid & 31;
    const unsigned FULL = 0xffffffffu;
    for (int i = tid; i < 192 * 64; i += 512) {
        int row = i >> 6, e = i & 63;
        smw[WIH_OFF + row * 65 + e] = wih[i];
        smw[WHH_OFF + row * 65 + e] = whh[i];
    }
    for (int i = tid; i < 128 * 64; i += 512)
        smw[RW1_OFF + (i >> 6) * 65 + (i & 63)] = rw1[i];
    for (int i = tid; i < 64 * 128; i += 512)
        smw[RW2_OFF + (i >> 7) * 129 + (i & 127)] = rw2[i];
    for (int i = tid; i < 64 * 32; i += 512)
        smw[VW_OFF + (i >> 5) * 33 + (i & 31)] = vw[i];
    __syncthreads();
    float S = g_S[r];
    float u = g_Uf[r * ID + lane] / S;
    float up0 = 0.f, up1 = 0.f;
#pragma unroll
    for (int c = 0; c < 32; c++) {
        float uc = __shfl_sync(FULL, u, c);
        up0 += uc * smw[VW_OFF + lane * 33 + c];
        up1 += uc * smw[VW_OFF + (lane + 32) * 33 + c];
    }
    float hp0 = g_slots[r * SD + lane], hp1 = g_slots[r * SD + 32 + lane];
    float xg[6], hg[6];
#pragma unroll
    for (int k = 0; k < 6; k++) { xg[k] = bih[lane + 32 * k]; hg[k] = bhh[lane + 32 * k]; }
    for (int e = 0; e < 32; e++) {
        float ue = __shfl_sync(FULL, up0, e), he = __shfl_sync(FULL, hp0, e);
#pragma unroll
        for (int k = 0; k < 6; k++) {
            xg[k] += ue * smw[WIH_OFF + (lane + 32 * k) * 65 + e];
            hg[k] += he * smw[WHH_OFF + (lane + 32 * k) * 65 + e];
        }
    }
    for (int e = 0; e < 32; e++) {
        float ue = __shfl_sync(FULL, up1, e), he = __shfl_sync(FULL, hp1, e);
#pragma unroll
        for (int k = 0; k < 6; k++) {
            xg[k] += ue * smw[WIH_OFF + (lane + 32 * k) * 65 + 32 + e];
            hg[k] += he * smw[WHH_OFF + (lane + 32 * k) * 65 + 32 + e];
        }
    }
    float h[2];
#pragma unroll
    for (int k2 = 0; k2 < 2; k2++) {
        float rg = sigmoidf_(xg[k2] + hg[k2]);
        float zg = sigmoidf_(xg[2 + k2] + hg[2 + k2]);
        float ng = tanhf(xg[4 + k2] + rg * hg[4 + k2]);
        h[k2] = (1.f - zg) * ng + zg * (k2 ? hp1 : hp0);
    }
    float s = h[0] + h[1];
#pragma unroll
    for (int o = 16; o; o >>= 1) s += __shfl_xor_sync(FULL, s, o);
    float m = s * (1.f / 64.f);
    float d0 = h[0] - m, d1 = h[1] - m;
    float vv = d0 * d0 + d1 * d1;
#pragma unroll
    for (int o = 16; o; o >>= 1) vv += __shfl_xor_sync(FULL, vv, o);
    float inv = rsqrtf(vv * (1.f / 64.f) + 1e-5f);
    float y0 = d0 * inv * rlng[lane] + rlnb[lane];
    float y1 = d1 * inv * rlng[lane + 32] + rlnb[lane + 32];
    float t[4];
#pragma unroll
    for (int k = 0; k < 4; k++) t[k] = rb1[lane + 32 * k];
    for (int e = 0; e < 32; e++) {
        float ye = __shfl_sync(FULL, y0, e);
#pragma unroll
        for (int k = 0; k < 4; k++) t[k] += ye * smw[RW1_OFF + (lane + 32 * k) * 65 + e];
    }
    for (int e = 0; e < 32; e++) {
        float ye = __shfl_sync(FULL, y1, e);
#pragma unroll
        for (int k = 0; k < 4; k++) t[k] += ye * smw[RW1_OFF + (lane + 32 * k) * 65 + 32 + e];
    }
#pragma unroll
    for (int k = 0; k < 4; k++) t[k] = fmaxf(t[k], 0.f);
    float r0 = rb2[lane], r1 = rb2[lane + 32];
#pragma unroll
    for (int k = 0; k < 4; k++)
        for (int e = 0; e < 32; e++) {
            float tm = __shfl_sync(FULL, t[k], e);
            r0 += tm * smw[RW2_OFF + lane * 129 + 32 * k + e];
            r1 += tm * smw[RW2_OFF + (lane + 32) * 129 + 32 * k + e];
        }
    float o0 = h[0] + r0, o1 = h[1] + r1;
    g_slots[r * SD + lane] = o0;
    g_slots[r * SD + 32 + lane] = o1;
    if (last) {
        out_slots[r * SD + lane] = o0;
        out_slots[r * SD + 32 + lane] = o1;
    }
}

extern "C" void kernel_launch(void* const* d_in, const int* in_sizes, int n_in,
                              void* d_out, int out_size) {
    (void)in_sizes; (void)n_in; (void)out_size;
    const float* slots = (const float*)d_in[0];
    const float* oin   = (const float*)d_in[1];
    const float* w1 = (const float*)d_in[2],  *b1 = (const float*)d_in[3];
    const float* w2 = (const float*)d_in[4],  *b2 = (const float*)d_in[5];
    const float* w3 = (const float*)d_in[6],  *b3 = (const float*)d_in[7];
    const float* kw = (const float*)d_in[8],  *vw = (const float*)d_in[9];
    const float* qlng = (const float*)d_in[10], *qlnb = (const float*)d_in[11];
    const float* qw = (const float*)d_in[12];
    const float* wih = (const float*)d_in[13], *whh = (const float*)d_in[14];
    const float* bih = (const float*)d_in[15], *bhh = (const float*)d_in[16];
    const float* rlng = (const float*)d_in[17], *rlnb = (const float*)d_in[18];
    const float* rw1 = (const float*)d_in[19], *rb1 = (const float*)d_in[20];
    const float* rw2 = (const float*)d_in[21], *rb2 = (const float*)d_in[22];
    const float* flng = (const float*)d_in[23], *flnb = (const float*)d_in[24];
    float* out = (float*)d_out;
    float* out_attn = out + NB * KS * SD;

    const int smem_sz = ABYTES + 3 * BGRP;   // 230400
    static int cfg_done = 0;
    if (!cfg_done) {
        cudaFuncSetAttribute(conv23_mma<2>, cudaFuncAttributeMaxDynamicSharedMemorySize, smem_sz);
        cudaFuncSetAttribute(conv23_mma<3>, cudaFuncAttributeMaxDynamicSharedMemorySize, smem_sz);
        cudaFuncSetAttribute(update_kernel, cudaFuncAttributeMaxDynamicSharedMemorySize, UPD_SMEM);
        cfg_done = 1;
    }
    init_slots_kernel<<<1, 1024>>>(slots);
    wprep_kernel<<<(27 * 32 * 64 + 255) / 256, 256>>>(w2, w3);
    conv1_kernel<<<dim3(5, 20, 2 * 20), 256>>>(oin, w1, b1);
    conv23_mma<2><<<dim3(G2 / 2, G2 / 2, NB), 320, smem_sz>>>(b2, nullptr, nullptr);
    conv23_mma<3><<<dim3(G3 / 2, G3 / 2, NB), 320, smem_sz>>>(b3, flng, flnb);
    for (int it = 0; it < 3; it++) {
        qk_kernel<<<1, 512>>>(qlng, qlnb, qw, kw);
        attn_kernel<<<dim3((N3 + 255) / 256, NB), 256>>>(out_attn, it == 2);
        update_kernel<<<1, 512, UPD_SMEM>>>(vw, wih, whh, bih, bhh, rlng, rlnb,
                                            rw1, rb1, rw2, rb2, out, it == 2);
    }
}

// round 17
// speedup vs baseline: 1.0765x; 1.0765x over previous
#include <cuda_runtime.h>
#include <cuda_bf16.h>
#include <cstdint>

#define NB 2
#define VD 4
#define ID 32
#define SD 64
#define KS 8
#define HD 128
#define G0 80
#define G1 78
#define G2 76
#define G3 74
#define N3 405224

__device__ uint4 g_x1b[(size_t)NB * G1 * G1 * 80 * 8];
__device__ uint4 g_x2b[(size_t)NB * G2 * G2 * 80 * 8];
__device__ float g_feat[(size_t)NB * N3 * ID];
__device__ uint4 g_wB2[27 * 4608 / 16];
__device__ uint4 g_wB3[27 * 4608 / 16];
__device__ float g_slots[NB * KS * SD];
__device__ float g_qk[NB * KS * ID];
__device__ float g_S[NB * KS];
__device__ float g_Uf[NB * KS * ID];

__device__ __forceinline__ float sigmoidf_(float x) { return 1.f / (1.f + expf(-x)); }
#define FMA2(acc, a, b) \
    asm("fma.rn.f32x2 %0, %1, %2, %3;" : "=l"(acc) : "l"(a), "l"(b), "l"(acc))
__device__ __forceinline__ unsigned long long dup2(float v) {
    unsigned long long r; unsigned u = __float_as_uint(v);
    asm("mov.b64 %0, {%1, %1};" : "=l"(r) : "r"(u)); return r;
}
__device__ __forceinline__ unsigned long long pack2(float lo, float hi) {
    unsigned long long r;
    asm("mov.b64 %0, {%1, %2};" : "=l"(r) : "r"(__float_as_uint(lo)), "r"(__float_as_uint(hi)));
    return r;
}
__device__ __forceinline__ void unpack2(unsigned long long p, float& lo, float& hi) {
    unsigned a, b; asm("mov.b64 {%0, %1}, %2;" : "=r"(a), "=r"(b) : "l"(p));
    lo = __uint_as_float(a); hi = __uint_as_float(b);
}
__device__ __forceinline__ void cp_async16(void* d, const void* s) {
    unsigned sa = (unsigned)__cvta_generic_to_shared(d);
    asm volatile("cp.async.cg.shared.global [%0], [%1], 16;" :: "r"(sa), "l"(s) : "memory");
}
__device__ __forceinline__ void ldsm_x4(uint32_t r[4], uint32_t saddr) {
    asm volatile("ldmatrix.sync.aligned.m8n8.x4.shared.b16 {%0,%1,%2,%3}, [%4];"
        : "=r"(r[0]), "=r"(r[1]), "=r"(r[2]), "=r"(r[3]) : "r"(saddr));
}
__device__ __forceinline__ void mma_bf16(float d[4], const uint32_t a[4], uint32_t b0, uint32_t b1) {
    asm volatile(
        "mma.sync.aligned.m16n8k16.row.col.f32.bf16.bf16.f32 "
        "{%0,%1,%2,%3}, {%4,%5,%6,%7}, {%8,%9}, {%0,%1,%2,%3};"
        : "+f"(d[0]), "+f"(d[1]), "+f"(d[2]), "+f"(d[3])
        : "r"(a[0]), "r"(a[1]), "r"(a[2]), "r"(a[3]), "r"(b0), "r"(b1));
}

__device__ __forceinline__ void store_hilo(uint4* dst, const float* v) {
    unsigned short hb[32], lb[32];
#pragma unroll
    for (int c = 0; c < 32; c++) {
        __nv_bfloat16 h = __float2bfloat16(v[c]);
        hb[c] = __bfloat16_as_ushort(h);
        lb[c] = __bfloat16_as_ushort(__float2bfloat16(v[c] - __bfloat162float(h)));
    }
#pragma unroll
    for (int j = 0; j < 4; j++) {
        uint4 q;
        q.x = hb[8*j+0] | ((uint32_t)hb[8*j+1] << 16);
        q.y = hb[8*j+2] | ((uint32_t)hb[8*j+3] << 16);
        q.z = hb[8*j+4] | ((uint32_t)hb[8*j+5] << 16);
        q.w = hb[8*j+6] | ((uint32_t)hb[8*j+7] << 16);
        dst[j] = q;
        q.x = lb[8*j+0] | ((uint32_t)lb[8*j+1] << 16);
        q.y = lb[8*j+2] | ((uint32_t)lb[8*j+3] << 16);
        q.z = lb[8*j+4] | ((uint32_t)lb[8*j+5] << 16);
        q.w = lb[8*j+6] | ((uint32_t)lb[8*j+7] << 16);
        dst[4 + j] = q;
    }
}

__global__ void init_slots_kernel(const float* __restrict__ s) {
    int t = threadIdx.x;
    if (t < NB * KS * SD) g_slots[t] = s[t];
}

__global__ void wprep_kernel(const float* __restrict__ w2, const float* __restrict__ w3) {
    int i = blockIdx.x * 256 + threadIdx.x;
    if (i >= 27 * 32 * 64) return;
    int k = i & 63, n = (i >> 6) & 31, tile = i >> 11;
    int dx = tile % 3, grp = tile / 3;
    int tap = (grp / 3) * 9 + (grp % 3) * 3 + dx;
    int cin = k & 31;
    bool take_hi = (k < 32);
    size_t dst = (size_t)tile * 4608 + n * 144 + k * 2;
    float a = w2[(n * ID + cin) * 27 + tap];
    __nv_bfloat16 h = __float2bfloat16(a);
    *(__nv_bfloat16*)((char*)g_wB2 + dst) = take_hi ? h : __float2bfloat16(a - __bfloat162float(h));
    a = w3[(n * ID + cin) * 27 + tap];
    h = __float2bfloat16(a);
    *(__nv_bfloat16*)((char*)g_wB3 + dst) = take_hi ? h : __float2bfloat16(a - __bfloat162float(h));
}

__global__ void conv1_kernel(const float* __restrict__ in, const float* __restrict__ w,
                             const float* __restrict__ bias) {
    __shared__ float xs[VD * 648];
    __shared__ float ws[VD * 27 * 32];
    __shared__ float bs[32];
    int tid = threadIdx.x;
    int b = blockIdx.z / 20, d0 = (blockIdx.z % 20) * 4, h0 = blockIdx.y * 4, w0 = blockIdx.x * 16;
    for (int i = tid; i < VD * 27 * 32; i += 256) {
        int co = i & 31, tap = (i >> 5) % 27, cin = i / (27 * 32);
        ws[i] = w[(co * VD + cin) * 27 + tap];
    }
    if (tid < 32) bs[tid] = bias[tid];
    for (int i = tid; i < VD * 648; i += 256) {
        int cin = i / 648, r = i % 648;
        int z = r / 108, y = (r % 108) / 18, x = r % 18;
        int gz = d0 + z, gy = h0 + y, gx = w0 + x;
        float v = 0.f;
        if (gz < G0 && gy < G0 && gx < G0)
            v = in[((b * VD + cin) * G0 + gz) * (G0 * G0) + gy * G0 + gx];
        xs[i] = v;
    }
    __syncthreads();
    int tx = tid & 15, ty = (tid >> 4) & 3, tz = tid >> 6;
    unsigned long long acc2[16];
#pragma unroll
    for (int p = 0; p < 16; p++) acc2[p] = 0ull;
    for (int cin = 0; cin < VD; cin++) {
        const float* xb = &xs[cin * 648 + tz * 108 + ty * 18 + tx];
        const float* wb = &ws[cin * 27 * 32];
#pragma unroll
        for (int tap = 0; tap < 27; tap++) {
            int dz = tap / 9, dy = (tap / 3) % 3, dx = tap % 3;
            unsigned long long xv2 = dup2(xb[dz * 108 + dy * 18 + dx]);
            const ulonglong2* w4 = (const ulonglong2*)&wb[tap * 32];
#pragma unroll
            for (int g = 0; g < 8; g++) {
                ulonglong2 q = w4[g];
                FMA2(acc2[2 * g + 0], q.x, xv2);
                FMA2(acc2[2 * g + 1], q.y, xv2);
            }
        }
    }
    int oz = d0 + tz, oy = h0 + ty, ox = w0 + tx;
    if (oz < G1 && oy < G1 && ox < G1) {
        float v[32];
#pragma unroll
        for (int p = 0; p < 16; p++) {
            float lo, hi; unpack2(acc2[p], lo, hi);
            v[2 * p + 0] = fmaxf(lo + bs[2 * p + 0], 0.f);
            v[2 * p + 1] = fmaxf(hi + bs[2 * p + 1], 0.f);
        }
        size_t row = ((size_t)(b * G1 + oz) * G1 + oy) * 80 + ox;
        store_hilo(g_x1b + row * 8, v);
    }
}

// conv2/3: 640 threads (20 warps), M=16 per warp, 4 output rows per CTA.
// Per kp-pair B fragments in registers; diag hi*hi + both cross terms; lo*lo skipped.
#define APITCH 11808
#define ABYTES (16 * APITCH)
#define BGRP 13824
template <int STAGE>
__global__ void __launch_bounds__(640, 1)
conv23_mma(const float* __restrict__ bias, const float* __restrict__ lng,
           const float* __restrict__ lnb) {
    constexpr int IDm = (STAGE == 2) ? G1 : G2;
    constexpr int OD  = (STAGE == 2) ? G2 : G3;
    const char* inb = (const char*)((STAGE == 2) ? g_x1b : g_x2b);
    const char* wB  = (const char*)((STAGE == 2) ? g_wB2 : g_wB3);
    extern __shared__ char sm[];
    int tid = threadIdx.x, w = tid >> 5, lane = tid & 31;
    int y0 = blockIdx.x * 2, z0 = blockIdx.y * 2, b = blockIdx.z;
    {
        const int per = (82 - IDm) * 8;
        for (int i = tid; i < 16 * per; i += 640) {
            int row = i / per, rem = i % per;
            *(float4*)(sm + row * APITCH + (IDm + rem / 8) * 144 + (rem & 7) * 16) =
                make_float4(0.f, 0.f, 0.f, 0.f);
        }
    }
    {
        const int per = IDm * 8;
        for (int i = tid; i < 16 * per; i += 640) {
            int row = i / per, rem = i % per;
            int vox = rem >> 3, c = rem & 7;
            size_t rowg = ((size_t)(b * IDm + (z0 + (row >> 2))) * IDm + (y0 + (row & 3))) * 80 + vox;
            cp_async16(sm + row * APITCH + vox * 144 + c * 16, inb + rowg * 128 + c * 16);
        }
    }
    for (int i = tid; i < BGRP / 16; i += 640)
        cp_async16(sm + ABYTES + i * 16, wB + (size_t)i * 16);
    asm volatile("cp.async.commit_group;" ::: "memory");

    int rowt = w / 5, xa = (w % 5) * 16;     // warp tile: row rowt (0..3), x block xa
    uint32_t smb = (uint32_t)__cvta_generic_to_shared(sm);
    uint32_t a_off = (uint32_t)(((lane & 7) + ((lane >> 3) & 1) * 8) * 144 + (lane >> 4) * 16);
    uint32_t b_off = (uint32_t)(((lane & 7) + (lane >> 4) * 8) * 144 + ((lane >> 3) & 1) * 16);
    float D[4][4];
#pragma unroll
    for (int j = 0; j < 4; j++)
#pragma unroll
        for (int q = 0; q < 4; q++) D[j][q] = 0.f;

    for (int g = 0; g < 9; g++) {
        int slot = g % 3;
        if (g < 8) {
            int nslot = (g + 1) % 3;
            for (int i = tid; i < BGRP / 16; i += 640)
                cp_async16(sm + ABYTES + nslot * BGRP + i * 16,
                           wB + (size_t)(g + 1) * BGRP + (size_t)i * 16);
            asm volatile("cp.async.commit_group;" ::: "memory");
            asm volatile("cp.async.wait_group 1;" ::: "memory");
        } else {
            asm volatile("cp.async.wait_group 0;" ::: "memory");
        }
        __syncthreads();
        int dz = g / 3, dy = g % 3;
        uint32_t sB = smb + ABYTES + slot * BGRP + b_off;
        uint32_t sA = smb + (((rowt >> 1) + dz) * 4 + (rowt & 1) + dy) * APITCH + a_off;
#pragma unroll
        for (int kp = 0; kp < 2; kp++) {
            const int kx = kp ^ 2;
            uint32_t Bk[3][2][4], Bx[3][2][4];
#pragma unroll
            for (int dx = 0; dx < 3; dx++) {
                uint32_t bt = sB + dx * 4608;
                ldsm_x4(Bk[dx][0], bt + kp * 32);
                ldsm_x4(Bk[dx][1], bt + kp * 32 + 16 * 144);
                ldsm_x4(Bx[dx][0], bt + kx * 32);
                ldsm_x4(Bx[dx][1], bt + kx * 32 + 16 * 144);
            }
#pragma unroll
            for (int dx = 0; dx < 3; dx++) {
                uint32_t A0[4], A1[4];
                ldsm_x4(A0, sA + (xa + dx) * 144 + kp * 32);
                ldsm_x4(A1, sA + (xa + dx) * 144 + kx * 32);
                // diag hi*hi
                mma_bf16(D[0], A0, Bk[dx][0][0], Bk[dx][0][1]);
                mma_bf16(D[1], A0, Bk[dx][0][2], Bk[dx][0][3]);
                mma_bf16(D[2], A0, Bk[dx][1][0], Bk[dx][1][1]);
                mma_bf16(D[3], A0, Bk[dx][1][2], Bk[dx][1][3]);
                // cross hi*lo
                mma_bf16(D[0], A0, Bx[dx][0][0], Bx[dx][0][1]);
                mma_bf16(D[1], A0, Bx[dx][0][2], Bx[dx][0][3]);
                mma_bf16(D[2], A0, Bx[dx][1][0], Bx[dx][1][1]);
                mma_bf16(D[3], A0, Bx[dx][1][2], Bx[dx][1][3]);
                // cross lo*hi
                mma_bf16(D[0], A1, Bk[dx][0][0], Bk[dx][0][1]);
                mma_bf16(D[1], A1, Bk[dx][0][2], Bk[dx][0][3]);
                mma_bf16(D[2], A1, Bk[dx][1][0], Bk[dx][1][1]);
                mma_bf16(D[3], A1, Bk[dx][1][2], Bk[dx][1][3]);
            }
        }
    }
    __syncthreads();
    float* Dsm = (float*)sm;
    int gid = lane >> 2, q4 = lane & 3;
    {
        int mbase = w * 16 + gid;
#pragma unroll
        for (int ns = 0; ns < 4; ns++) {
            int co = ns * 8 + q4 * 2;
            *(float2*)&Dsm[mbase * 38 + co]       = make_float2(D[ns][0], D[ns][1]);
            *(float2*)&Dsm[(mbase + 8) * 38 + co] = make_float2(D[ns][2], D[ns][3]);
        }
    }
    __syncthreads();
    if (tid < 320) {
        int m = tid, row = m / 80, x = m % 80;
        int zout = z0 + (row >> 1), yout = y0 + (row & 1);
        if (x < OD) {
            float v[32];
#pragma unroll
            for (int c = 0; c < 32; c++)
                v[c] = fmaxf(Dsm[m * 38 + c] + bias[c], 0.f);
            if (STAGE == 2) {
                size_t rowo = ((size_t)(b * G2 + zout) * G2 + yout) * 80 + x;
                store_hilo(g_x2b + rowo * 8, v);
            } else {
                float mn = 0.f;
#pragma unroll
                for (int c = 0; c < 32; c++) mn += v[c];
                mn *= (1.f / 32.f);
                float var = 0.f;
#pragma unroll
                for (int c = 0; c < 32; c++) { float d = v[c] - mn; var += d * d; }
                float inv = rsqrtf(var * (1.f / 32.f) + 1e-5f);
                size_t vox = ((size_t)zout * G3 + yout) * G3 + x;
                float4* fp = (float4*)&g_feat[((size_t)b * N3 + vox) * 32];
#pragma unroll
                for (int gq = 0; gq < 8; gq++) {
                    float4 o;
                    o.x = (v[4*gq+0] - mn) * inv * lng[4*gq+0] + lnb[4*gq+0];
                    o.y = (v[4*gq+1] - mn) * inv * lng[4*gq+1] + lnb[4*gq+1];
                    o.z = (v[4*gq+2] - mn) * inv * lng[4*gq+2] + lnb[4*gq+2];
                    o.w = (v[4*gq+3] - mn) * inv * lng[4*gq+3] + lnb[4*gq+3];
                    fp[gq] = o;
                }
            }
        }
    }
}

__global__ void qk_kernel(const float* __restrict__ qlng, const float* __restrict__ qlnb,
                          const float* __restrict__ qw, const float* __restrict__ kw) {
    __shared__ float qln_s[16][64];
    __shared__ float q_s[16][64];
    __shared__ float qw_s[64 * 65];
    __shared__ float kw_s[64 * 33];
    int tid = threadIdx.x, warp = tid >> 5, lane = tid & 31;
    const unsigned FULL = 0xffffffffu;
    if (tid < NB * KS) g_S[tid] = 0.f;
    if (tid < NB * KS * ID) g_Uf[tid] = 0.f;
    for (int i = tid; i < 64 * 64; i += 512) qw_s[(i >> 6) * 65 + (i & 63)] = qw[i];
    for (int i = tid; i < 64 * 32; i += 512) kw_s[(i >> 5) * 33 + (i & 31)] = kw[i];
    float x0 = g_slots[warp * SD + lane], x1 = g_slots[warp * SD + 32 + lane];
    float s = x0 + x1;
#pragma unroll
    for (int o = 16; o; o >>= 1) s += __shfl_xor_sync(FULL, s, o);
    float m = s * (1.f / 64.f);
    float d0 = x0 - m, d1 = x1 - m;
    float v = d0 * d0 + d1 * d1;
#pragma unroll
    for (int o = 16; o; o >>= 1) v += __shfl_xor_sync(FULL, v, o);
    float inv = rsqrtf(v * (1.f / 64.f) + 1e-5f);
    float qa = d0 * inv * qlng[lane] + qlnb[lane];
    float qb = d1 * inv * qlng[lane + 32] + qlnb[lane + 32];
    __syncthreads();
    qln_s[warp][lane] = qa;
    qln_s[warp][lane + 32] = qb;
    __syncwarp();
    float a0 = 0.f, a1 = 0.f;
    for (int e = 0; e < 64; e++) {
        float qe = qln_s[warp][e];
        a0 += qe * qw_s[lane * 65 + e];
        a1 += qe * qw_s[(lane + 32) * 65 + e];
    }
    q_s[warp][lane] = a0; q_s[warp][lane + 32] = a1;
    __syncwarp();
    float qk = 0.f;
    for (int d = 0; d < 64; d++) qk += q_s[warp][d] * kw_s[d * 33 + lane];
    g_qk[warp * ID + lane] = qk * 0.125f;
}

__global__ void attn_kernel(float* __restrict__ attn_out, int write_attn) {
    __shared__ float F[256 * 36];
    __shared__ float A[256 * 9];
    __shared__ float qks[KS * ID];
    int tid = threadIdx.x, b = blockIdx.y;
    int j = blockIdx.x * 256 + tid;
    qks[tid] = g_qk[b * KS * ID + tid];
    bool ok = j < N3;
    unsigned long long f2[16];
    if (ok) {
        const float4* fp = (const float4*)&g_feat[((size_t)b * N3 + j) * 32];
#pragma unroll
        for (int g = 0; g < 8; g++) {
            float4 q = fp[g];
            f2[2 * g + 0] = pack2(q.x, q.y);
            f2[2 * g + 1] = pack2(q.z, q.w);
        }
    } else {
#pragma unroll
        for (int p = 0; p < 16; p++) f2[p] = 0ull;
    }
    {
        float2* Fp = (float2*)&F[tid * 36];
#pragma unroll
        for (int p = 0; p < 16; p++) {
            float lo, hi; unpack2(f2[p], lo, hi);
            Fp[p] = make_float2(lo, hi);
        }
    }
    __syncthreads();
    unsigned long long acc2[8];
#pragma unroll
    for (int i = 0; i < 8; i++) acc2[i] = 0ull;
#pragma unroll
    for (int p = 0; p < 16; p++) {
        unsigned long long fp2 = f2[p];
#pragma unroll
        for (int i = 0; i < 8; i++)
            FMA2(acc2[i], fp2, *(const unsigned long long*)&qks[i * 32 + 2 * p]);
    }
    float a[8];
    if (ok) {
        float d[8];
#pragma unroll
        for (int i = 0; i < 8; i++) {
            float lo, hi; unpack2(acc2[i], lo, hi);
            d[i] = lo + hi;
        }
        float m = d[0];
#pragma unroll
        for (int i = 1; i < 8; i++) m = fmaxf(m, d[i]);
        float sum = 0.f;
#pragma unroll
        for (int i = 0; i < 8; i++) { a[i] = __expf(d[i] - m); sum += a[i]; }
        float rs = 1.f / sum;
#pragma unroll
        for (int i = 0; i < 8; i++) a[i] = a[i] * rs + 1e-8f;
        if (write_attn)
#pragma unroll
            for (int i = 0; i < 8; i++)
                attn_out[(size_t)(b * KS + i) * N3 + j] = a[i];
    } else {
#pragma unroll
        for (int i = 0; i < 8; i++) a[i] = 0.f;
    }
#pragma unroll
    for (int i = 0; i < 8; i++) A[tid * 9 + i] = a[i];
    __syncthreads();
    const unsigned FULL = 0xffffffffu;
    int ii = tid >> 5, lane = tid & 31;
    int cp = lane & 15, ph = lane >> 4;
    unsigned long long s2a = 0ull, s2b = 0ull, s2c = 0ull, s2d = 0ull;
    int pb = ph * 128;
#pragma unroll 8
    for (int p0 = 0; p0 < 128; p0 += 4) {
        int p = pb + p0;
        FMA2(s2a, dup2(A[(p + 0) * 9 + ii]), *(const unsigned long long*)&F[(p + 0) * 36 + 2 * cp]);
        FMA2(s2b, dup2(A[(p + 1) * 9 + ii]), *(const unsigned long long*)&F[(p + 1) * 36 + 2 * cp]);
        FMA2(s2c, dup2(A[(p + 2) * 9 + ii]), *(const unsigned long long*)&F[(p + 2) * 36 + 2 * cp]);
        FMA2(s2d, dup2(A[(p + 3) * 9 + ii]), *(const unsigned long long*)&F[(p + 3) * 36 + 2 * cp]);
    }
    float slo, shi, t1, t2;
    unpack2(s2a, slo, shi);
    unpack2(s2b, t1, t2); slo += t1; shi += t2;
    unpack2(s2c, t1, t2); slo += t1; shi += t2;
    unpack2(s2d, t1, t2); slo += t1; shi += t2;
    slo += __shfl_xor_sync(FULL, slo, 16);
    shi += __shfl_xor_sync(FULL, shi, 16);
    if (ph == 0) {
        atomicAdd(&g_Uf[(b * KS + ii) * ID + 2 * cp + 0], slo);
        atomicAdd(&g_Uf[(b * KS + ii) * ID + 2 * cp + 1], shi);
    }
    float ss = 0.f;
#pragma unroll
    for (int q = 0; q < 8; q++) ss += A[(lane + 32 * q) * 9 + ii];
#pragma unroll
    for (int o = 16; o; o >>= 1) ss += __shfl_xor_sync(FULL, ss, o);
    if (lane == 0) atomicAdd(&g_S[b * KS + ii], ss);
}

#define WIH_OFF 0
#define WHH_OFF 12480
#define RW1_OFF 24960
#define RW2_OFF 33280
#define VW_OFF  41536
#define UPD_SMEM ((41536 + 2112) * 4)
__global__ void update_kernel(const float* __restrict__ vw, const float* __restrict__ wih,
                              const float* __restrict__ whh, const float* __restrict__ bih,
                              const float* __restrict__ bhh, const float* __restrict__ rlng,
                              const float* __restrict__ rlnb, const float* __restrict__ rw1,
                              const float* __restrict__ rb1, const float* __restrict__ rw2,
                              const float* __restrict__ rb2, float* __restrict__ out_slots,
                              int last) {
    extern __shared__ float smw[];
    int tid = threadIdx.x, r = tid >> 5, lane = tid & 31;
    const unsigned FULL = 0xffffffffu;
    for (int i = tid; i < 192 * 64; i += 512) {
        int row = i >> 6, e = i & 63;
        smw[WIH_OFF + row * 65 + e] = wih[i];
        smw[WHH_OFF + row * 65 + e] = whh[i];
    }
    for (int i = tid; i < 128 * 64; i += 512)
        smw[RW1_OFF + (i >> 6) * 65 + (i & 63)] = rw1[i];
    for (int i = tid; i < 64 * 128; i += 512)
        smw[RW2_OFF + (i >> 7) * 129 + (i & 127)] = rw2[i];
    for (int i = tid; i < 64 * 32; i += 512)
        smw[VW_OFF + (i >> 5) * 33 + (i & 31)] = vw[i];
    __syncthreads();
    float S = g_S[r];
    float u = g_Uf[r * ID + lane] / S;
    float up0 = 0.f, up1 = 0.f;
#pragma unroll
    for (int c = 0; c < 32; c++) {
        float uc = __shfl_sync(FULL, u, c);
        up0 += uc * smw[VW_OFF + lane * 33 + c];
        up1 += uc * smw[VW_OFF + (lane + 32) * 33 + c];
    }
    float hp0 = g_slots[r * SD + lane], hp1 = g_slots[r * SD + 32 + lane];
    float xg[6], hg[6];
#pragma unroll
    for (int k = 0; k < 6; k++) { xg[k] = bih[lane + 32 * k]; hg[k] = bhh[lane + 32 * k]; }
    for (int e = 0; e < 32; e++) {
        float ue = __shfl_sync(FULL, up0, e), he = __shfl_sync(FULL, hp0, e);
#pragma unroll
        for (int k = 0; k < 6; k++) {
            xg[k] += ue * smw[WIH_OFF + (lane + 32 * k) * 65 + e];
            hg[k] += he * smw[WHH_OFF + (lane + 32 * k) * 65 + e];
        }
    }
    for (int e = 0; e < 32; e++) {
        float ue = __shfl_sync(FULL, up1, e), he = __shfl_sync(FULL, hp1, e);
#pragma unroll
        for (int k = 0; k < 6; k++) {
            xg[k] += ue * smw[WIH_OFF + (lane + 32 * k) * 65 + 32 + e];
            hg[k] += he * smw[WHH_OFF + (lane + 32 * k) * 65 + 32 + e];
        }
    }
    float h[2];
#pragma unroll
    for (int k2 = 0; k2 < 2; k2++) {
        float rg = sigmoidf_(xg[k2] + hg[k2]);
        float zg = sigmoidf_(xg[2 + k2] + hg[2 + k2]);
        float ng = tanhf(xg[4 + k2] + rg * hg[4 + k2]);
        h[k2] = (1.f - zg) * ng + zg * (k2 ? hp1 : hp0);
    }
    float s = h[0] + h[1];
#pragma unroll
    for (int o = 16; o; o >>= 1) s += __shfl_xor_sync(FULL, s, o);
    float m = s * (1.f / 64.f);
    float d0 = h[0] - m, d1 = h[1] - m;
    float vv = d0 * d0 + d1 * d1;
#pragma unroll
    for (int o = 16; o; o >>= 1) vv += __shfl_xor_sync(FULL, vv, o);
    float inv = rsqrtf(vv * (1.f / 64.f) + 1e-5f);
    float y0 = d0 * inv * rlng[lane] + rlnb[lane];
    float y1 = d1 * inv * rlng[lane + 32] + rlnb[lane + 32];
    float t[4];
#pragma unroll
    for (int k = 0; k < 4; k++) t[k] = rb1[lane + 32 * k];
    for (int e = 0; e < 32; e++) {
        float ye = __shfl_sync(FULL, y0, e);
#pragma unroll
        for (int k = 0; k < 4; k++) t[k] += ye * smw[RW1_OFF + (lane + 32 * k) * 65 + e];
    }
    for (int e = 0; e < 32; e++) {
        float ye = __shfl_sync(FULL, y1, e);
#pragma unroll
        for (int k = 0; k < 4; k++) t[k] += ye * smw[RW1_OFF + (lane + 32 * k) * 65 + 32 + e];
    }
#pragma unroll
    for (int k = 0; k < 4; k++) t[k] = fmaxf(t[k], 0.f);
    float r0 = rb2[lane], r1 = rb2[lane + 32];
#pragma unroll
    for (int k = 0; k < 4; k++)
        for (int e = 0; e < 32; e++) {
            float tm = __shfl_sync(FULL, t[k], e);
            r0 += tm * smw[RW2_OFF + lane * 129 + 32 * k + e];
            r1 += tm * smw[RW2_OFF + (lane + 32) * 129 + 32 * k + e];
        }
    float o0 = h[0] + r0, o1 = h[1] + r1;
    g_slots[r * SD + lane] = o0;
    g_slots[r * SD + 32 + lane] = o1;
    if (last) {
        out_slots[r * SD + lane] = o0;
        out_slots[r * SD + 32 + lane] = o1;
    }
}

extern "C" void kernel_launch(void* const* d_in, const int* in_sizes, int n_in,
                              void* d_out, int out_size) {
    (void)in_sizes; (void)n_in; (void)out_size;
    const float* slots = (const float*)d_in[0];
    const float* oin   = (const float*)d_in[1];
    const float* w1 = (const float*)d_in[2],  *b1 = (const float*)d_in[3];
    const float* w2 = (const float*)d_in[4],  *b2 = (const float*)d_in[5];
    const float* w3 = (const float*)d_in[6],  *b3 = (const float*)d_in[7];
    const float* kw = (const float*)d_in[8],  *vw = (const float*)d_in[9];
    const float* qlng = (const float*)d_in[10], *qlnb = (const float*)d_in[11];
    const float* qw = (const float*)d_in[12];
    const float* wih = (const float*)d_in[13], *whh = (const float*)d_in[14];
    const float* bih = (const float*)d_in[15], *bhh = (const float*)d_in[16];
    const float* rlng = (const float*)d_in[17], *rlnb = (const float*)d_in[18];
    const float* rw1 = (const float*)d_in[19], *rb1 = (const float*)d_in[20];
    const float* rw2 = (const float*)d_in[21], *rb2 = (const float*)d_in[22];
    const float* flng = (const float*)d_in[23], *flnb = (const float*)d_in[24];
    float* out = (float*)d_out;
    float* out_attn = out + NB * KS * SD;

    const int smem_sz = ABYTES + 3 * BGRP;   // 230400
    static int cfg_done = 0;
    if (!cfg_done) {
        cudaFuncSetAttribute(conv23_mma<2>, cudaFuncAttributeMaxDynamicSharedMemorySize, smem_sz);
        cudaFuncSetAttribute(conv23_mma<3>, cudaFuncAttributeMaxDynamicSharedMemorySize, smem_sz);
        cudaFuncSetAttribute(update_kernel, cudaFuncAttributeMaxDynamicSharedMemorySize, UPD_SMEM);
        cfg_done = 1;
    }
    init_slots_kernel<<<1, 1024>>>(slots);
    wprep_kernel<<<(27 * 32 * 64 + 255) / 256, 256>>>(w2, w3);
    conv1_kernel<<<dim3(5, 20, 2 * 20), 256>>>(oin, w1, b1);
    conv23_mma<2><<<dim3(G2 / 2, G2 / 2, NB), 640, smem_sz>>>(b2, nullptr, nullptr);
    conv23_mma<3><<<dim3(G3 / 2, G3 / 2, NB), 640, smem_sz>>>(b3, flng, flnb);
    for (int it = 0; it < 3; it++) {
        qk_kernel<<<1, 512>>>(qlng, qlnb, qw, kw);
        attn_kernel<<<dim3((N3 + 255) / 256, NB), 256>>>(out_attn, it == 2);
        update_kernel<<<1, 512, UPD_SMEM>>>(vw, wih, whh, bih, bhh, rlng, rlnb,
                                            rw1, rb1, rw2, rb2, out, it == 2);
    }
}